// round 7
// baseline (speedup 1.0000x reference)
#include <cuda_runtime.h>
#include <cuda_fp16.h>
#include <cstdint>

// Problem dims
#define S_LEN 1024
#define BATCH 64
#define IDIM  512
#define HDIM  2048
#define ODIM  512
#define MTOT  (S_LEN * BATCH)   // 65536

// ---------------------------------------------------------------------------
// Device scratch (no cudaMalloc allowed)
// ---------------------------------------------------------------------------
__device__ __half g_Xh[(size_t)MTOT * IDIM];        // 64 MB   fp16 X
__device__ __half g_Wh[(size_t)HDIM * IDIM];        // 2 MB    fp16 W_ih
__device__ __half g_uh[(size_t)MTOT * HDIM];        // 256 MB  u (fp16)
__device__ float  g_h [(size_t)BATCH * HDIM];       // 512 KB  h_final[b][h]
__device__ float  g_part[(size_t)32 * BATCH * ODIM];// 4 MB    split-K partials

// Sync flags (zeroed each run by zero_flags_kernel):
// [0,8192)      tile flags: GEMM tile (i=M-tile 0..511, j=N-tile 0..15) -> i*16+j
// [8192,8704)   flagX per 128-row X chunk (512)
// [8704,9216)   cntX per chunk
// [9216]        flagW   [9217] cntW
#define FT_OFF 0
#define FX_OFF 8192
#define CX_OFF 8704
#define FW_OFF 9216
#define CW_OFF 9217
#define SYNC_TOTAL 9218
__device__ unsigned g_sync[SYNC_TOTAL];

// ---------------------------------------------------------------------------
// Helpers
// ---------------------------------------------------------------------------
__device__ __forceinline__ void cp_async16(uint32_t saddr, const void* gptr) {
    asm volatile("cp.async.cg.shared.global [%0], [%1], 16;\n"
                 :: "r"(saddr), "l"(gptr) : "memory");
}
#define CP_COMMIT() asm volatile("cp.async.commit_group;\n" ::: "memory")
#define CP_WAIT(N)  asm volatile("cp.async.wait_group %0;\n" :: "n"(N) : "memory")

__device__ __forceinline__ void st_release(unsigned* p, unsigned v) {
    asm volatile("st.release.gpu.global.u32 [%0], %1;" :: "l"(p), "r"(v) : "memory");
}
__device__ __forceinline__ unsigned ld_acquire(const unsigned* p) {
    unsigned v;
    asm volatile("ld.acquire.gpu.global.u32 %0, [%1];" : "=r"(v) : "l"(p) : "memory");
    return v;
}

struct alignas(16) H8 { __half2 a, b, c, d; };

// ---------------------------------------------------------------------------
// Kernel 0: zero sync flags (graph replays reuse device state)
// ---------------------------------------------------------------------------
__global__ void zero_flags_kernel() {
    int i = blockIdx.x * blockDim.x + threadIdx.x;
    if (i < SYNC_TOTAL) g_sync[i] = 0;
}

// ---------------------------------------------------------------------------
// Kernel 1: fused fp32 -> fp16 conversion prepass (X then W in one grid).
// Sets per-chunk completion flags so the GEMM (PDL secondary) can start
// consuming while later chunks still convert.
// ---------------------------------------------------------------------------
#define NX_H8 (MTOT * IDIM / 8)          // 4,194,304
#define NW_H8 (HDIM * IDIM / 8)          // 131,072
#define NX_CTAS (NX_H8 / 256)            // 16384 (32 CTAs per 128-row chunk)
#define NW_CTAS (NW_H8 / 256)            // 512

__global__ void cvt_kernel(const float4* __restrict__ X,
                           const float4* __restrict__ W) {
#if __CUDA_ARCH__ >= 900
    cudaTriggerProgrammaticLaunchCompletion();
#endif
    const int bid = blockIdx.x;
    int i = bid * 256 + threadIdx.x;
    const float4* src;
    H8* dst;
    int j;
    if (i < NX_H8) {
        src = X;  dst = reinterpret_cast<H8*>(g_Xh);  j = i;
    } else {
        src = W;  dst = reinterpret_cast<H8*>(g_Wh);  j = i - NX_H8;
    }
    float4 v0 = src[2 * j], v1 = src[2 * j + 1];
    H8 o;
    o.a = __floats2half2_rn(v0.x, v0.y);
    o.b = __floats2half2_rn(v0.z, v0.w);
    o.c = __floats2half2_rn(v1.x, v1.y);
    o.d = __floats2half2_rn(v1.z, v1.w);
    dst[j] = o;

    __threadfence();
    __syncthreads();
    if (threadIdx.x == 0) {
        if (bid < NX_CTAS) {
            int chunk = bid >> 5;                       // 32 CTAs per chunk
            if (atomicAdd(&g_sync[CX_OFF + chunk], 1u) == 31u)
                st_release(&g_sync[FX_OFF + chunk], 1u);
        } else {
            if (atomicAdd(&g_sync[CW_OFF], 1u) == (unsigned)(NW_CTAS - 1))
                st_release(&g_sync[FW_OFF], 1u);
        }
    }
}

// ---------------------------------------------------------------------------
// Kernel 2: u = Xh @ Wh^T via mma.sync.m16n8k16 (FROZEN compute core, ~275
// TF/s at the legacy fp16 HMMA ceiling).  Added: entry poll on cvt flags
// (PDL overlap-safe) and per-tile release flag for the scan.
// ---------------------------------------------------------------------------
#define BM 128
#define BN 128
#define BKH 32
#define KTILES (IDIM / BKH)        // 16
#define NSTG 3
#define LDAH 40
#define STAGE_HALFS (BM * LDAH)

__global__ __launch_bounds__(256, 2) void gemm_u_kernel() {
#if __CUDA_ARCH__ >= 900
    cudaTriggerProgrammaticLaunchCompletion();
#endif
    __shared__ __half sA[NSTG][STAGE_HALFS];
    __shared__ __half sB[NSTG][STAGE_HALFS];

    const int tid  = threadIdx.x;
    const int lane = tid & 31;
    const int warp = tid >> 5;
    const int wm   = warp >> 1;
    const int wn   = warp & 1;
    const int g    = lane >> 2;
    const int tg   = lane & 3;

    const int m0 = blockIdx.y * BM;
    const int n0 = blockIdx.x * BN;

    // Wait for cvt: our A rows (chunk == blockIdx.y) and all of W.
    if (tid == 0) {
        while (!ld_acquire(&g_sync[FX_OFF + blockIdx.y])) {}
        while (!ld_acquire(&g_sync[FW_OFF])) {}
    }
    __syncthreads();

    const uint32_t sA_base = (uint32_t)__cvta_generic_to_shared(&sA[0][0]);
    const uint32_t sB_base = (uint32_t)__cvta_generic_to_shared(&sB[0][0]);

    float c[2][8][4];
#pragma unroll
    for (int mi = 0; mi < 2; mi++)
#pragma unroll
        for (int ni = 0; ni < 8; ni++)
#pragma unroll
            for (int r = 0; r < 4; r++) c[mi][ni][r] = 0.0f;

    auto loadAB = [&](int stage, int kt) {
#pragma unroll
        for (int i = 0; i < 2; i++) {
            int lin = tid + i * 256;
            int row = lin >> 2, c16 = lin & 3;
            cp_async16(sA_base + (stage * STAGE_HALFS + row * LDAH + c16 * 8) * 2,
                       g_Xh + (size_t)(m0 + row) * IDIM + kt * BKH + c16 * 8);
            cp_async16(sB_base + (stage * STAGE_HALFS + row * LDAH + c16 * 8) * 2,
                       g_Wh + (size_t)(n0 + row) * IDIM + kt * BKH + c16 * 8);
        }
    };

    loadAB(0, 0); CP_COMMIT();
    loadAB(1, 1); CP_COMMIT();

    for (int kt = 0; kt < KTILES; ++kt) {
        if (kt < KTILES - 1) { CP_WAIT(1); } else { CP_WAIT(0); }
        __syncthreads();

        if (kt + 2 < KTILES) { loadAB((kt + 2) % NSTG, kt + 2); CP_COMMIT(); }

        const __half* A = sA[kt % NSTG];
        const __half* B = sB[kt % NSTG];
#pragma unroll
        for (int kf = 0; kf < 2; ++kf) {
            const int k = kf * 16;
            uint32_t a[2][4], bf[8][2];
#pragma unroll
            for (int mi = 0; mi < 2; mi++) {
                int r = wm * 32 + mi * 16 + g;
                a[mi][0] = *(const uint32_t*)&A[r * LDAH + k + tg * 2];
                a[mi][1] = *(const uint32_t*)&A[(r + 8) * LDAH + k + tg * 2];
                a[mi][2] = *(const uint32_t*)&A[r * LDAH + k + 8 + tg * 2];
                a[mi][3] = *(const uint32_t*)&A[(r + 8) * LDAH + k + 8 + tg * 2];
            }
#pragma unroll
            for (int ni = 0; ni < 8; ni++) {
                int cc = wn * 64 + ni * 8 + g;
                bf[ni][0] = *(const uint32_t*)&B[cc * LDAH + k + tg * 2];
                bf[ni][1] = *(const uint32_t*)&B[cc * LDAH + k + 8 + tg * 2];
            }
#pragma unroll
            for (int mi = 0; mi < 2; mi++)
#pragma unroll
                for (int ni = 0; ni < 8; ni++) {
                    asm volatile(
                        "mma.sync.aligned.m16n8k16.row.col.f32.f16.f16.f32 "
                        "{%0,%1,%2,%3}, {%4,%5,%6,%7}, {%8,%9}, {%0,%1,%2,%3};"
                        : "+f"(c[mi][ni][0]), "+f"(c[mi][ni][1]),
                          "+f"(c[mi][ni][2]), "+f"(c[mi][ni][3])
                        : "r"(a[mi][0]), "r"(a[mi][1]), "r"(a[mi][2]), "r"(a[mi][3]),
                          "r"(bf[ni][0]), "r"(bf[ni][1]));
                }
        }
        __syncthreads();
    }

#pragma unroll
    for (int mi = 0; mi < 2; mi++) {
#pragma unroll
        for (int ni = 0; ni < 8; ni++) {
            int r     = m0 + wm * 32 + mi * 16 + g;
            int cbase = n0 + wn * 64 + ni * 8 + 2 * tg;
            __half2 v0 = __floats2half2_rn(c[mi][ni][0], c[mi][ni][1]);
            __half2 v1 = __floats2half2_rn(c[mi][ni][2], c[mi][ni][3]);
            *reinterpret_cast<__half2*>(g_uh + (size_t)r * HDIM + cbase)       = v0;
            *reinterpret_cast<__half2*>(g_uh + (size_t)(r + 8) * HDIM + cbase) = v1;
        }
    }

    // Publish this tile for the scan.
    __threadfence();
    __syncthreads();
    if (tid == 0)
        st_release(&g_sync[FT_OFF + blockIdx.y * 16 + blockIdx.x], 1u);
}

// ---------------------------------------------------------------------------
// Kernel 3: sequential scan h = |u_t + hh*h|, fp16 u, 2 channels/thread.
// One 64-thread CTA per (b, N-tile j): 1024 CTAs (balanced).  Depth-32
// prefetch ring; before loading each next window, acquire-poll the 16 GEMM
// tile flags covering it (lanes 0..15 spin, usually already set).
// ---------------------------------------------------------------------------
#define SCAN_DEPTH 32

__device__ __forceinline__ void wait_tiles16(const unsigned* ft, int t0, int lane) {
    if (lane < 16) {
        while (!ld_acquire(ft + (size_t)(t0 + lane) * 16)) {}
    }
    __syncwarp();
}

__global__ void scan_kernel(const float* __restrict__ hh) {
    const int b    = blockIdx.x >> 4;
    const int j    = blockIdx.x & 15;          // N-tile (128 h columns)
    const int t    = threadIdx.x;              // 0..63
    const int lane = t & 31;
    const int hc   = j * 64 + t;               // half2 column 0..1023
    const float a0 = hh[2 * hc];
    const float a1 = hh[2 * hc + 1];
    const __half2* p = reinterpret_cast<const __half2*>(g_uh)
                       + (size_t)b * (HDIM / 2) + hc;
    const size_t stride = (size_t)BATCH * HDIM / 2;   // 65536 half2/step
    const unsigned* ft = g_sync + FT_OFF + j;         // flag[i*16 + j]

    wait_tiles16(ft, 0, lane);                 // window 0: tiles 0..15
    __half2 buf[SCAN_DEPTH];
#pragma unroll
    for (int i = 0; i < SCAN_DEPTH; i++) buf[i] = p[(size_t)i * stride];

    float h0 = 0.0f, h1 = 0.0f;
    for (int s0 = 0; s0 < S_LEN; s0 += SCAN_DEPTH) {
        if (s0 + SCAN_DEPTH < S_LEN)
            wait_tiles16(ft, s0 / 2 + 16, lane);   // tiles of next window
#pragma unroll
        for (int i = 0; i < SCAN_DEPTH; i++) {
            float2 u = __half22float2(buf[i]);
            int ns = s0 + SCAN_DEPTH + i;
            if (ns < S_LEN) buf[i] = p[(size_t)ns * stride];
            h0 = fabsf(fmaf(a0, h0, u.x));
            h1 = fabsf(fmaf(a1, h1, u.y));
        }
    }
    const int ch2 = b * (HDIM / 2) + hc;
    *reinterpret_cast<float2*>(g_h + 2 * ch2) = make_float2(h0, h1);
}

// ---------------------------------------------------------------------------
// Kernel 4/5: split-K output GEMM (KSLICES=32 for occupancy) + reduce
// ---------------------------------------------------------------------------
#define KSLICES 32

__global__ __launch_bounds__(256) void out_partial_kernel(const float* __restrict__ W_ho) {
    __shared__ float sh[64][65];
    __shared__ float sw[64][65];
    const int tid = threadIdx.x;
    const int tx = tid & 15, ty = tid >> 4;
    const int o0 = blockIdx.x * 64;
    const int ks = blockIdx.y;
    const int kbase = ks * 64;

    float acc[4][4];
#pragma unroll
    for (int i = 0; i < 4; i++)
#pragma unroll
        for (int j = 0; j < 4; j++) acc[i][j] = 0.0f;

#pragma unroll
    for (int i = 0; i < 16; i++) {
        int lin = tid + i * 256;
        int row = lin >> 6, col = lin & 63;
        sh[row][col] = g_h[(size_t)row * HDIM + kbase + col];
        sw[row][col] = W_ho[(size_t)(o0 + row) * HDIM + kbase + col];
    }
    __syncthreads();
#pragma unroll 8
    for (int k = 0; k < 64; k++) {
        float av[4], bv[4];
#pragma unroll
        for (int i = 0; i < 4; i++) av[i] = sh[ty * 4 + i][k];
#pragma unroll
        for (int j = 0; j < 4; j++) bv[j] = sw[tx * 4 + j][k];
#pragma unroll
        for (int i = 0; i < 4; i++)
#pragma unroll
            for (int j = 0; j < 4; j++) acc[i][j] = fmaf(av[i], bv[j], acc[i][j]);
    }

#pragma unroll
    for (int i = 0; i < 4; i++)
#pragma unroll
        for (int j = 0; j < 4; j++) {
            int bb = ty * 4 + i;
            int o  = o0 + tx * 4 + j;
            g_part[(size_t)ks * (BATCH * ODIM) + bb * ODIM + o] = acc[i][j];
        }
}

__global__ void out_reduce_kernel(const float* __restrict__ b_ho, float* __restrict__ Y) {
    int i = blockIdx.x * blockDim.x + threadIdx.x;
    float s = b_ho[i & (ODIM - 1)];
#pragma unroll
    for (int k = 0; k < KSLICES; k++) s += g_part[(size_t)k * (BATCH * ODIM) + i];
    Y[i] = s;
}

// ---------------------------------------------------------------------------
// Launch — GEMM and scan use programmatic dependent launch so they overlap
// the tail of their predecessor; correctness is guaranteed by the flag
// handshakes regardless of actual overlap.
// ---------------------------------------------------------------------------
extern "C" void kernel_launch(void* const* d_in, const int* in_sizes, int n_in,
                              void* d_out, int out_size) {
    const float* X    = (const float*)d_in[0];   // [1024,64,512]
    const float* W_ih = (const float*)d_in[1];   // [2048,512]
    const float* hh   = (const float*)d_in[2];   // [2048]
    const float* W_ho = (const float*)d_in[3];   // [512,2048]
    const float* b_ho = (const float*)d_in[4];   // [512]
    float* Y = (float*)d_out;                    // [64,512]

    // 0) reset flags (graph replays reuse device state)
    zero_flags_kernel<<<(SYNC_TOTAL + 255) / 256, 256>>>();

    // 1) conversion prepass (sets chunk flags progressively)
    cvt_kernel<<<NX_CTAS + NW_CTAS, 256>>>((const float4*)X, (const float4*)W_ih);

    cudaLaunchAttribute pdl[1];
    pdl[0].id = cudaLaunchAttributeProgrammaticStreamSerialization;
    pdl[0].val.programmaticStreamSerializationAllowed = 1;

    // 2) big GEMM (PDL secondary of cvt; polls cvt flags at entry)
    {
        cudaLaunchConfig_t cfg = {};
        cfg.gridDim  = dim3(HDIM / BN, MTOT / BM);   // (16, 512)
        cfg.blockDim = dim3(256);
        cfg.stream   = 0;
        cfg.attrs    = pdl;
        cfg.numAttrs = 1;
        cudaLaunchKernelEx(&cfg, gemm_u_kernel);
    }

    // 3) scan (PDL secondary of GEMM; polls tile flags per window)
    {
        cudaLaunchConfig_t cfg = {};
        cfg.gridDim  = dim3(BATCH * 16);             // 1024 CTAs
        cfg.blockDim = dim3(64);
        cfg.stream   = 0;
        cfg.attrs    = pdl;
        cfg.numAttrs = 1;
        cudaLaunchKernelEx(&cfg, scan_kernel, hh);
    }

    // 4) output GEMM (split-K) + reduce (plain, serialized after scan)
    dim3 ogrid(ODIM / 64, KSLICES);
    out_partial_kernel<<<ogrid, 256>>>(W_ho);
    out_reduce_kernel<<<(BATCH * ODIM) / 256, 256>>>(b_ho, Y);
}

// round 8
// speedup vs baseline: 1.0502x; 1.0502x over previous
#include <cuda_runtime.h>
#include <cuda_fp16.h>
#include <cstdint>

// Problem dims
#define S_LEN 1024
#define BATCH 64
#define IDIM  512
#define HDIM  2048
#define ODIM  512
#define MTOT  (S_LEN * BATCH)   // 65536

// ---------------------------------------------------------------------------
// Device scratch (no cudaMalloc allowed)
// ---------------------------------------------------------------------------
__device__ __half g_Wh[(size_t)HDIM * IDIM];        // 2 MB    fp16 W_ih
__device__ __half g_uh[(size_t)MTOT * HDIM];        // 256 MB  u (fp16)
__device__ float  g_h [(size_t)BATCH * HDIM];       // 512 KB  h_final[b][h]
__device__ float  g_part[(size_t)32 * BATCH * ODIM];// 4 MB    split-K partials

// ---------------------------------------------------------------------------
// Helpers
// ---------------------------------------------------------------------------
__device__ __forceinline__ void cp_async16(uint32_t saddr, const void* gptr) {
    asm volatile("cp.async.cg.shared.global [%0], [%1], 16;\n"
                 :: "r"(saddr), "l"(gptr) : "memory");
}
#define CP_COMMIT() asm volatile("cp.async.commit_group;\n" ::: "memory")
#define CP_WAIT(N)  asm volatile("cp.async.wait_group %0;\n" :: "n"(N) : "memory")

__device__ __forceinline__ uint32_t f2_to_h2(float x, float y) {
    __half2 h = __floats2half2_rn(x, y);
    return *reinterpret_cast<uint32_t*>(&h);
}

struct alignas(16) H8 { __half2 a, b, c, d; };

// ---------------------------------------------------------------------------
// Kernel 1: W fp32 -> fp16 (tiny: 6 MB traffic)
// ---------------------------------------------------------------------------
#define NW_H8 (HDIM * IDIM / 8)          // 131,072

__global__ void cvtW_kernel(const float4* __restrict__ W) {
    int i = blockIdx.x * blockDim.x + threadIdx.x;
    float4 v0 = W[2 * i], v1 = W[2 * i + 1];
    H8 o;
    o.a = __floats2half2_rn(v0.x, v0.y);
    o.b = __floats2half2_rn(v0.z, v0.w);
    o.c = __floats2half2_rn(v1.x, v1.y);
    o.d = __floats2half2_rn(v1.z, v1.w);
    reinterpret_cast<H8*>(g_Wh)[i] = o;
}

// ---------------------------------------------------------------------------
// Kernel 2: u = fp16(X) @ Wh^T via mma.sync.m16n8k16.
// A is read DIRECTLY as fp32 from the input (no prepass): cp.async fp32
// tiles into smem; fragments convert fp32->fp16 in-register (cvt.rn.f16x2).
// The GEMM is HMMA-throughput-bound with ~450 idle issue-slots per k-tile,
// so the extra LDS.64+cvt traffic is free; +64MB DRAM is absorbed by slack.
// CTA tile 128x128, BK=32, 3-stage pipeline, 8 warps (4x2), 2 CTAs/SM.
// ---------------------------------------------------------------------------
#define BM 128
#define BN 128
#define BKH 32                      // K elements per tile
#define KTILES (IDIM / BKH)         // 16
#define NSTG 3
#define LDAF 40                     // A row stride in floats (160 B)
#define LDAH 40                     // B row stride in halves (80 B)
#define STAGE_AF (BM * LDAF)        // floats per A stage
#define STAGE_BH (BM * LDAH)        // halves per B stage
#define A_SMEM_BYTES (NSTG * STAGE_AF * 4)   // 61440
#define B_SMEM_BYTES (NSTG * STAGE_BH * 2)   // 30720
#define GEMM_SMEM (A_SMEM_BYTES + B_SMEM_BYTES)  // 92160

__global__ __launch_bounds__(256, 2) void gemm_u_kernel(const float* __restrict__ X) {
    extern __shared__ char smem[];
    float*  sAf = reinterpret_cast<float*>(smem);
    __half* sBh = reinterpret_cast<__half*>(smem + A_SMEM_BYTES);

    const int tid  = threadIdx.x;
    const int lane = tid & 31;
    const int warp = tid >> 5;
    const int wm   = warp >> 1;   // 0..3
    const int wn   = warp & 1;    // 0..1
    const int g    = lane >> 2;   // 0..7
    const int tg   = lane & 3;    // 0..3

    const int m0 = blockIdx.y * BM;
    const int n0 = blockIdx.x * BN;

    const uint32_t sA_base = (uint32_t)__cvta_generic_to_shared(sAf);
    const uint32_t sB_base = (uint32_t)__cvta_generic_to_shared(sBh);

    float c[2][8][4];
#pragma unroll
    for (int mi = 0; mi < 2; mi++)
#pragma unroll
        for (int ni = 0; ni < 8; ni++)
#pragma unroll
            for (int r = 0; r < 4; r++) c[mi][ni][r] = 0.0f;

    // A: 128 rows x 32 floats = 1024 16B-chunks -> 4/thread.
    // B: 128 rows x 32 halves =  512 16B-chunks -> 2/thread.
    auto loadAB = [&](int stage, int kt) {
#pragma unroll
        for (int i = 0; i < 4; i++) {
            int lin = tid + i * 256;
            int row = lin >> 3, c16 = lin & 7;
            cp_async16(sA_base + (stage * STAGE_AF + row * LDAF + c16 * 4) * 4,
                       X + (size_t)(m0 + row) * IDIM + kt * BKH + c16 * 4);
        }
#pragma unroll
        for (int i = 0; i < 2; i++) {
            int lin = tid + i * 256;
            int row = lin >> 2, c16 = lin & 3;
            cp_async16(sB_base + (stage * STAGE_BH + row * LDAH + c16 * 8) * 2,
                       g_Wh + (size_t)(n0 + row) * IDIM + kt * BKH + c16 * 8);
        }
    };

    loadAB(0, 0); CP_COMMIT();
    loadAB(1, 1); CP_COMMIT();

    for (int kt = 0; kt < KTILES; ++kt) {
        if (kt < KTILES - 1) { CP_WAIT(1); } else { CP_WAIT(0); }
        __syncthreads();

        if (kt + 2 < KTILES) { loadAB((kt + 2) % NSTG, kt + 2); CP_COMMIT(); }

        const float*  A = sAf + (kt % NSTG) * STAGE_AF;
        const __half* B = sBh + (kt % NSTG) * STAGE_BH;
#pragma unroll
        for (int kf = 0; kf < 2; ++kf) {
            const int k = kf * 16;
            uint32_t a[2][4], bf[8][2];
#pragma unroll
            for (int mi = 0; mi < 2; mi++) {
                int r = wm * 32 + mi * 16 + g;
                float2 f0 = *(const float2*)&A[r * LDAF + k + 2 * tg];
                float2 f1 = *(const float2*)&A[(r + 8) * LDAF + k + 2 * tg];
                float2 f2 = *(const float2*)&A[r * LDAF + k + 8 + 2 * tg];
                float2 f3 = *(const float2*)&A[(r + 8) * LDAF + k + 8 + 2 * tg];
                a[mi][0] = f2_to_h2(f0.x, f0.y);
                a[mi][1] = f2_to_h2(f1.x, f1.y);
                a[mi][2] = f2_to_h2(f2.x, f2.y);
                a[mi][3] = f2_to_h2(f3.x, f3.y);
            }
#pragma unroll
            for (int ni = 0; ni < 8; ni++) {
                int cc = wn * 64 + ni * 8 + g;
                bf[ni][0] = *(const uint32_t*)&B[cc * LDAH + k + tg * 2];
                bf[ni][1] = *(const uint32_t*)&B[cc * LDAH + k + 8 + tg * 2];
            }
#pragma unroll
            for (int mi = 0; mi < 2; mi++)
#pragma unroll
                for (int ni = 0; ni < 8; ni++) {
                    asm volatile(
                        "mma.sync.aligned.m16n8k16.row.col.f32.f16.f16.f32 "
                        "{%0,%1,%2,%3}, {%4,%5,%6,%7}, {%8,%9}, {%0,%1,%2,%3};"
                        : "+f"(c[mi][ni][0]), "+f"(c[mi][ni][1]),
                          "+f"(c[mi][ni][2]), "+f"(c[mi][ni][3])
                        : "r"(a[mi][0]), "r"(a[mi][1]), "r"(a[mi][2]), "r"(a[mi][3]),
                          "r"(bf[ni][0]), "r"(bf[ni][1]));
                }
        }
        __syncthreads();
    }

#pragma unroll
    for (int mi = 0; mi < 2; mi++) {
#pragma unroll
        for (int ni = 0; ni < 8; ni++) {
            int r     = m0 + wm * 32 + mi * 16 + g;
            int cbase = n0 + wn * 64 + ni * 8 + 2 * tg;
            __half2 v0 = __floats2half2_rn(c[mi][ni][0], c[mi][ni][1]);
            __half2 v1 = __floats2half2_rn(c[mi][ni][2], c[mi][ni][3]);
            *reinterpret_cast<__half2*>(g_uh + (size_t)r * HDIM + cbase)       = v0;
            *reinterpret_cast<__half2*>(g_uh + (size_t)(r + 8) * HDIM + cbase) = v1;
        }
    }
}

// ---------------------------------------------------------------------------
// Kernel 3: sequential scan h = |u_t + hh*h|, fp16 u, 2 channels/thread.
// 1024 CTAs x 64 thr (balanced ~6.9 CTA/SM), depth-32 prefetch ring
// (8 MB in flight).  No flags, no polls.
// ---------------------------------------------------------------------------
#define SCAN_DEPTH 32

__global__ void scan_kernel(const float* __restrict__ hh) {
    const int ch2 = blockIdx.x * blockDim.x + threadIdx.x;   // half2 index
    const int hpair = (2 * ch2) & (HDIM - 1);
    const float a0 = hh[hpair];
    const float a1 = hh[hpair + 1];
    const __half2* p = reinterpret_cast<const __half2*>(g_uh) + ch2;
    const size_t stride = (size_t)BATCH * HDIM / 2;          // 65536 half2s

    __half2 buf[SCAN_DEPTH];
#pragma unroll
    for (int i = 0; i < SCAN_DEPTH; i++) buf[i] = p[(size_t)i * stride];

    float h0 = 0.0f, h1 = 0.0f;
    for (int s0 = 0; s0 < S_LEN; s0 += SCAN_DEPTH) {
#pragma unroll
        for (int i = 0; i < SCAN_DEPTH; i++) {
            float2 u = __half22float2(buf[i]);
            int ns = s0 + SCAN_DEPTH + i;
            if (ns < S_LEN) buf[i] = p[(size_t)ns * stride];
            h0 = fabsf(fmaf(a0, h0, u.x));
            h1 = fabsf(fmaf(a1, h1, u.y));
        }
    }
    *reinterpret_cast<float2*>(g_h + 2 * ch2) = make_float2(h0, h1);
}

// ---------------------------------------------------------------------------
// Kernel 4/5: split-K output GEMM (KSLICES=32) + reduce
// ---------------------------------------------------------------------------
#define KSLICES 32

__global__ __launch_bounds__(256) void out_partial_kernel(const float* __restrict__ W_ho) {
    __shared__ float sh[64][65];
    __shared__ float sw[64][65];
    const int tid = threadIdx.x;
    const int tx = tid & 15, ty = tid >> 4;
    const int o0 = blockIdx.x * 64;
    const int ks = blockIdx.y;
    const int kbase = ks * 64;

    float acc[4][4];
#pragma unroll
    for (int i = 0; i < 4; i++)
#pragma unroll
        for (int j = 0; j < 4; j++) acc[i][j] = 0.0f;

#pragma unroll
    for (int i = 0; i < 16; i++) {
        int lin = tid + i * 256;
        int row = lin >> 6, col = lin & 63;
        sh[row][col] = g_h[(size_t)row * HDIM + kbase + col];
        sw[row][col] = W_ho[(size_t)(o0 + row) * HDIM + kbase + col];
    }
    __syncthreads();
#pragma unroll 8
    for (int k = 0; k < 64; k++) {
        float av[4], bv[4];
#pragma unroll
        for (int i = 0; i < 4; i++) av[i] = sh[ty * 4 + i][k];
#pragma unroll
        for (int j = 0; j < 4; j++) bv[j] = sw[tx * 4 + j][k];
#pragma unroll
        for (int i = 0; i < 4; i++)
#pragma unroll
            for (int j = 0; j < 4; j++) acc[i][j] = fmaf(av[i], bv[j], acc[i][j]);
    }

#pragma unroll
    for (int i = 0; i < 4; i++)
#pragma unroll
        for (int j = 0; j < 4; j++) {
            int bb = ty * 4 + i;
            int o  = o0 + tx * 4 + j;
            g_part[(size_t)ks * (BATCH * ODIM) + bb * ODIM + o] = acc[i][j];
        }
}

__global__ void out_reduce_kernel(const float* __restrict__ b_ho, float* __restrict__ Y) {
    int i = blockIdx.x * blockDim.x + threadIdx.x;
    float s = b_ho[i & (ODIM - 1)];
#pragma unroll
    for (int k = 0; k < KSLICES; k++) s += g_part[(size_t)k * (BATCH * ODIM) + i];
    Y[i] = s;
}

// ---------------------------------------------------------------------------
// Launch
// ---------------------------------------------------------------------------
extern "C" void kernel_launch(void* const* d_in, const int* in_sizes, int n_in,
                              void* d_out, int out_size) {
    const float* X    = (const float*)d_in[0];   // [1024,64,512]
    const float* W_ih = (const float*)d_in[1];   // [2048,512]
    const float* hh   = (const float*)d_in[2];   // [2048]
    const float* W_ho = (const float*)d_in[3];   // [512,2048]
    const float* b_ho = (const float*)d_in[4];   // [512]
    float* Y = (float*)d_out;                    // [64,512]

    // 1) W fp16 prepass (X conversion is fused into the GEMM)
    cvtW_kernel<<<NW_H8 / 256, 256>>>((const float4*)W_ih);

    // 2) big GEMM u = fp16(X) @ Wh^T (fp16 mma, fp32 accum, dynamic smem)
    cudaFuncSetAttribute(gemm_u_kernel,
                         cudaFuncAttributeMaxDynamicSharedMemorySize, GEMM_SMEM);
    dim3 ggrid(HDIM / BN, MTOT / BM);  // (16, 512) x-major: N-tiles share A in L2
    gemm_u_kernel<<<ggrid, 256, GEMM_SMEM>>>(X);

    // 3) sequential scan
    scan_kernel<<<(BATCH * HDIM / 2) / 64, 64>>>(hh);

    // 4) output GEMM (split-K) + reduce
    dim3 ogrid(ODIM / 64, KSLICES);
    out_partial_kernel<<<ogrid, 256>>>(W_ho);
    out_reduce_kernel<<<(BATCH * ODIM) / 256, 256>>>(b_ho, Y);
}